// round 16
// baseline (speedup 1.0000x reference)
#include <cuda_runtime.h>
#include <cuda_bf16.h>
#include <math.h>
#include <cstdint>

#define BB 8
#define TT 2048
#define CC 1024
#define HH 64

// x as blocked swizzled 64x64 chunk-tiles: [(m64*16+kc)*2+hl][4096]
// unit(r,c) = r*64 + (((c>>3) ^ (r&7))<<3) + (c&7)
__device__ __nv_bfloat16 g_xT[256*16*2*4096];
// W^T chunk-tiles: [(kc*3+nsub)*2+hl][4096]
__device__ __nv_bfloat16 g_wTt[16*3*2*4096];

// Q/K/V^T blocked swizzled 64x64 tiles: [(b*32+tile)*2+hl][4096]
__device__ __nv_bfloat16 g_qT[8*32*2*4096];   // [t-row][h-col], pre-scaled x0.125*log2e
__device__ __nv_bfloat16 g_kT[8*32*2*4096];
__device__ __nv_bfloat16 g_vT[8*32*2*4096];   // [h-row][t-col]

__device__ int g_ctr  = 0;
__device__ int g_done = 0;

// split-tile partials (qt>=16, 2 segments)
__device__ float g_po[8*16*2*64*64];
__device__ float g_pm[8*16*2*64];
__device__ float g_pl[8*16*2*64];
__device__ int   g_cnt[8*16];

// ---- mma.sync m16n8k16 bf16 (sm_80 baseline) ----
__device__ __forceinline__ void mma16816(float* c, const uint32_t* a, const uint32_t* b) {
    asm volatile(
        "mma.sync.aligned.m16n8k16.row.col.f32.bf16.bf16.f32 "
        "{%0,%1,%2,%3}, {%4,%5,%6,%7}, {%8,%9}, {%0,%1,%2,%3};"
        : "+f"(c[0]), "+f"(c[1]), "+f"(c[2]), "+f"(c[3])
        : "r"(a[0]), "r"(a[1]), "r"(a[2]), "r"(a[3]), "r"(b[0]), "r"(b[1]));
}
__device__ __forceinline__ void ldsm4(uint32_t* r, uint32_t addr) {
    asm volatile("ldmatrix.sync.aligned.m8n8.x4.shared.b16 {%0,%1,%2,%3}, [%4];"
        : "=r"(r[0]), "=r"(r[1]), "=r"(r[2]), "=r"(r[3]) : "r"(addr) : "memory");
}

// ---- bulk async copy + mbarrier (sm_90 baseline PTX) ----
#define BULK(dst, srcptr, bytes, mbar) \
    asm volatile("cp.async.bulk.shared::cta.global.mbarrier::complete_tx::bytes [%0], [%1], %2, [%3];" \
        :: "r"(dst), "l"(srcptr), "r"(bytes), "r"(mbar) : "memory")
#define MBAR_INIT(a, c) asm volatile("mbarrier.init.shared.b64 [%0], %1;" :: "r"(a), "r"(c) : "memory")
#define MBAR_EXPECT_TX(a, tx) \
    asm volatile("mbarrier.arrive.expect_tx.shared.b64 _, [%0], %1;" :: "r"(a), "r"(tx) : "memory")
#define MBAR_WAIT(a, ph) do { \
    uint32_t _m = (a), _p = (ph), _d; \
    asm volatile("{\n\t.reg .pred p;\n\tmbarrier.try_wait.parity.acquire.cta.shared::cta.b64 p, [%1], %2;\n\tselp.b32 %0, 1, 0, p;\n\t}" \
        : "=r"(_d) : "r"(_m), "r"(_p) : "memory"); \
    if (!_d) { \
        asm volatile("{\n\t.reg .pred P1;\n\tWL_%=:\n\tmbarrier.try_wait.parity.acquire.cta.shared::cta.b64 P1, [%0], %1, 0x989680;\n\t@P1 bra.uni WD_%=;\n\tbra.uni WL_%=;\n\tWD_%=:\n\t}" \
            :: "r"(_m), "r"(_p) : "memory"); \
    } } while (0)

__device__ __forceinline__ uint32_t smem_u32(const void* p) {
    uint32_t a;
    asm("{ .reg .u64 t; cvta.to.shared.u64 t, %1; cvt.u32.u64 %0, t; }" : "=r"(a) : "l"(p));
    return a;
}
__device__ __forceinline__ float ex2(float x) {
    float y; asm("ex2.approx.f32 %0, %1;" : "=f"(y) : "f"(x)); return y;
}
__device__ __forceinline__ uint32_t hi2(float a, float b) {
    return ((uint32_t)__bfloat16_as_ushort(__float2bfloat16(b)) << 16) |
           (uint32_t)__bfloat16_as_ushort(__float2bfloat16(a));
}
__device__ __forceinline__ uint32_t lo2(float a, float b) {
    float ra = a - __bfloat162float(__float2bfloat16(a));
    float rb = b - __bfloat162float(__float2bfloat16(b));
    return hi2(ra, rb);
}

// ---------------------------------------------------------------------------
// Prep kernels (R15)
// ---------------------------------------------------------------------------
__global__ __launch_bounds__(256) void wprep_kernel(
    const float* __restrict__ Wq, const float* __restrict__ Wk,
    const float* __restrict__ Wv)
{
    int idx = blockIdx.x * 256 + threadIdx.x;
    int n  = idx >> 7;
    int gq = idx & 127;
    int k0 = gq * 8;
    const float* W = (n < 64) ? Wq : (n < 128) ? Wk : Wv;
    int h = n & 63;
    int nsub = n >> 6, r = n & 63;
    int kc = k0 >> 6, ccg = (k0 & 63) >> 3;
    int u = r * 64 + (((ccg) ^ (r & 7)) << 3);
    size_t tb = ((size_t)(kc * 3 + nsub) * 2) * 4096;
    uint32_t hv[4], lv[4];
    #pragma unroll
    for (int i = 0; i < 4; i++) {
        float a = W[(size_t)(k0 + 2 * i) * HH + h];
        float c = W[(size_t)(k0 + 2 * i + 1) * HH + h];
        hv[i] = hi2(a, c);
        lv[i] = lo2(a, c);
    }
    *(uint4*)&g_wTt[tb + u]        = *(uint4*)hv;
    *(uint4*)&g_wTt[tb + 4096 + u] = *(uint4*)lv;
}

__global__ __launch_bounds__(256) void xprep_kernel(const float* __restrict__ x)
{
    const int stride = gridDim.x * blockDim.x;
    for (int idx = blockIdx.x * 256 + threadIdx.x; idx < BB*TT*CC/8; idx += stride) {
        int m  = idx >> 7;
        int k0 = (idx & 127) * 8;
        float4 v0 = *(const float4*)&x[(size_t)m * CC + k0];
        float4 v1 = *(const float4*)&x[(size_t)m * CC + k0 + 4];
        uint32_t hv[4], lv[4];
        hv[0] = hi2(v0.x, v0.y);  lv[0] = lo2(v0.x, v0.y);
        hv[1] = hi2(v0.z, v0.w);  lv[1] = lo2(v0.z, v0.w);
        hv[2] = hi2(v1.x, v1.y);  lv[2] = lo2(v1.x, v1.y);
        hv[3] = hi2(v1.z, v1.w);  lv[3] = lo2(v1.z, v1.w);
        int m64 = m >> 6, r = m & 63;
        int kc = k0 >> 6, ccg = (k0 & 63) >> 3;
        int u = r * 64 + ((ccg ^ (r & 7)) << 3);
        size_t tb = ((size_t)(m64 * 16 + kc) * 2) * 4096;
        *(uint4*)&g_xT[tb + u]        = *(uint4*)hv;
        *(uint4*)&g_xT[tb + 4096 + u] = *(uint4*)lv;
    }
}

// ---------------------------------------------------------------------------
// Projection GEMM (R15): bulk-copy loads, 128 CTAs x 256 thr, K chunks of 64.
// ---------------------------------------------------------------------------
#define PROJ_SMEM 163840

__global__ __launch_bounds__(256, 1) void proj_mma_kernel()
{
    extern __shared__ __nv_bfloat16 sb[];
    const uint32_t sbase = smem_u32(sb);
    __shared__ __align__(8) unsigned long long smb[2];
    const uint32_t mb0 = smem_u32(&smb[0]);
    const uint32_t mb1 = smem_u32(&smb[1]);

    const int tid  = threadIdx.x;
    const int wid  = tid >> 5;
    const int lane = tid & 31;
    const int g    = lane >> 2;
    const int tg   = lane & 3;
    const int m0   = blockIdx.x * 128;
    const int m64b = blockIdx.x * 2;
    const int m0w  = (wid >> 1) * 32;
    const int n0w  = (wid & 1) * 96;

    const int m_off = (lane & 7) + ((lane >> 3) & 1) * 8;
    const int kA8   = (lane >> 4);
    const int n_off = (lane & 7) + ((lane >> 4) & 1) * 8;
    const int kB8   = ((lane >> 3) & 1);

    auto issue_chunk = [&](int kc, int s) {
        uint32_t mb = s ? mb1 : mb0;
        uint32_t st = sbase + 2 * (s * 40960);
        MBAR_EXPECT_TX(mb, 81920);
        #pragma unroll
        for (int sub = 0; sub < 2; sub++) {
            const __nv_bfloat16* src = g_xT + ((size_t)((m64b + sub) * 16 + kc) * 2) * 4096;
            BULK(st + 2 * (sub * 8192),        src,        8192, mb);
            BULK(st + 2 * (sub * 8192 + 4096), src + 4096, 8192, mb);
        }
        #pragma unroll
        for (int sub = 0; sub < 3; sub++) {
            const __nv_bfloat16* src = g_wTt + ((size_t)(kc * 3 + sub) * 2) * 4096;
            BULK(st + 2 * (16384 + sub * 8192),        src,        8192, mb);
            BULK(st + 2 * (16384 + sub * 8192 + 4096), src + 4096, 8192, mb);
        }
    };

    if (tid == 0) {
        MBAR_INIT(mb0, 1);
        MBAR_INIT(mb1, 1);
    }
    __syncthreads();
    if (tid == 0) {
        issue_chunk(0, 0);
        issue_chunk(1, 1);
    }

    float acc[2][12][4];
    #pragma unroll
    for (int mt = 0; mt < 2; mt++)
        #pragma unroll
        for (int nt = 0; nt < 12; nt++)
            #pragma unroll
            for (int i = 0; i < 4; i++) acc[mt][nt][i] = 0.f;

    int ph0 = 0, ph1 = 0;
    for (int kc = 0; kc < 16; kc++) {
        const int s = kc & 1;
        if (s) { MBAR_WAIT(mb1, ph1); ph1 ^= 1; }
        else   { MBAR_WAIT(mb0, ph0); ph0 ^= 1; }

        const uint32_t st = sbase + 2 * (s * 40960);

        #pragma unroll
        for (int i = 0; i < 4; i++) {
            uint32_t ah[2][4], al[2][4];
            #pragma unroll
            for (int mt = 0; mt < 2; mt++) {
                int row = m0w + mt * 16 + m_off;
                int sub = row >> 6, r = row & 63;
                int u = r * 64 + (((2 * i + kA8) ^ (r & 7)) << 3);
                ldsm4(ah[mt], st + 2 * (sub * 8192 + u));
                ldsm4(al[mt], st + 2 * (sub * 8192 + 4096 + u));
            }
            #pragma unroll
            for (int p = 0; p < 6; p++) {
                int row = n0w + p * 16 + n_off;
                int sub = row >> 6, r = row & 63;
                int u = r * 64 + (((2 * i + kB8) ^ (r & 7)) << 3);
                uint32_t bh[4], bl[4];
                ldsm4(bh, st + 2 * (16384 + sub * 8192 + u));
                ldsm4(bl, st + 2 * (16384 + sub * 8192 + 4096 + u));
                #pragma unroll
                for (int hf = 0; hf < 2; hf++) {
                    int nt = p * 2 + hf;
                    #pragma unroll
                    for (int mt = 0; mt < 2; mt++) {
                        mma16816(acc[mt][nt], ah[mt], bh + hf * 2);
                        mma16816(acc[mt][nt], ah[mt], bl + hf * 2);
                        mma16816(acc[mt][nt], al[mt], bh + hf * 2);
                    }
                }
            }
        }
        __syncthreads();
        if (tid == 0 && kc + 2 < 16) issue_chunk(kc + 2, s);
    }

    // ---- epilogue: blocked swizzled tiles ----
    const int b     = m0 >> 11;
    const int t0    = m0 & 2047;
    const int tile0 = b * 32 + (t0 >> 6);
    const float QSC = 0.125f * 1.44269504088896f;
    __nv_bfloat16* sTh = sb;
    __nv_bfloat16* sTl = sb + 64 * 136;

    #pragma unroll
    for (int nt = 0; nt < 12; nt++) {
        int nbase = n0w + nt * 8;
        #pragma unroll
        for (int mt = 0; mt < 2; mt++) {
            int row = m0w + mt * 16 + g;
            float c0 = acc[mt][nt][0], c1 = acc[mt][nt][1];
            float c2 = acc[mt][nt][2], c3 = acc[mt][nt][3];
            if (nbase < 128) {
                __nv_bfloat16* base;
                int col;
                if (nbase < 64) {
                    c0 *= QSC; c1 *= QSC; c2 *= QSC; c3 *= QSC;
                    base = g_qT; col = nbase + 2 * tg;
                } else {
                    base = g_kT; col = nbase - 64 + 2 * tg;
                }
                int tA = tile0 + (row >> 6);
                int r0 = row & 63;
                int r1 = r0 + 8;
                int u0 = r0 * 64 + ((((col >> 3) ^ (r0 & 7)) << 3)) + (col & 7);
                int u1 = r1 * 64 + ((((col >> 3) ^ (r1 & 7)) << 3)) + (col & 7);
                size_t tb = (size_t)(tA * 2) * 4096;
                *(uint32_t*)&base[tb + u0]        = hi2(c0, c1);
                *(uint32_t*)&base[tb + 4096 + u0] = lo2(c0, c1);
                *(uint32_t*)&base[tb + u1]        = hi2(c2, c3);
                *(uint32_t*)&base[tb + 4096 + u1] = lo2(c2, c3);
            } else {
                int h = nbase - 128 + 2 * tg;
                __nv_bfloat16 h0 = __float2bfloat16(c0), h1 = __float2bfloat16(c1);
                __nv_bfloat16 h2 = __float2bfloat16(c2), h3 = __float2bfloat16(c3);
                sTh[h * 136 + row]           = h0;
                sTh[(h + 1) * 136 + row]     = h1;
                sTh[h * 136 + row + 8]       = h2;
                sTh[(h + 1) * 136 + row + 8] = h3;
                sTl[h * 136 + row]           = __float2bfloat16(c0 - __bfloat162float(h0));
                sTl[(h + 1) * 136 + row]     = __float2bfloat16(c1 - __bfloat162float(h1));
                sTl[h * 136 + row + 8]       = __float2bfloat16(c2 - __bfloat162float(h2));
                sTl[(h + 1) * 136 + row + 8] = __float2bfloat16(c3 - __bfloat162float(h3));
            }
        }
    }
    __syncthreads();
    #pragma unroll
    for (int t = 0; t < 8; t++) {
        int e   = tid + t * 256;
        int arr = e >> 10;
        int ee  = e & 1023;
        int h   = ee >> 4;
        int q   = ee & 15;
        int vt  = tile0 + (q >> 3);
        int tg8 = q & 7;
        int u   = h * 64 + ((tg8 ^ (h & 7)) << 3);
        uint4 v4 = *(const uint4*)&(arr ? sTl : sTh)[h * 136 + q * 8];
        *(uint4*)&g_vT[((size_t)(vt * 2 + arr)) * 4096 + u] = v4;
    }
}

// ---------------------------------------------------------------------------
// Attention: software-pipelined — S(t+1) interleaved with softmax/PV(t).
// Bulk tile loads, 384 jobs, 304 CTAs.
// smem units: Qh@0 Ql@4096; stage s @8192+s*16384: Kh+0 Kl+4096 Vh+8192 Vl+12288
// ---------------------------------------------------------------------------
#define ATTN_CTAS 304
#define ATTN_JOBS 384
#define ATTN_SMEM 81920

__global__ __launch_bounds__(128, 1) void attn_mma_kernel(float* __restrict__ out)
{
    extern __shared__ __nv_bfloat16 sab[];
    const uint32_t sbase = smem_u32(sab);
    __shared__ __align__(8) unsigned long long smb[3];
    __shared__ int sJob;
    __shared__ int sLast;

    const uint32_t mbq  = smem_u32(&smb[0]);
    const uint32_t mbs0 = smem_u32(&smb[1]);
    const uint32_t mbs1 = smem_u32(&smb[2]);

    const int tid  = threadIdx.x;
    const int wid  = tid >> 5;
    const int lane = tid & 31;
    const int g    = lane >> 2;
    const int tg   = lane & 3;
    const int rw   = wid * 16;

    const int m_off = (lane & 7) + ((lane >> 3) & 1) * 8;
    const int kA8   = (lane >> 4);
    const int n_off = (lane & 7) + ((lane >> 4) & 1) * 8;
    const int kB8   = ((lane >> 3) & 1);

    const int qrow  = rw + m_off;
    const int qrx   = qrow & 7;

    for (;;) {
        if (tid == 0) sJob = atomicAdd(&g_ctr, 1);
        __syncthreads();
        const int job = sJob;
        if (job >= ATTN_JOBS) break;

        int qt, b, segid, seg0, segn, split;
        if (job < 256) {
            qt    = 31 - (job >> 4);
            b     = (job >> 1) & 7;
            segid = job & 1;
            split = 1;
            int total = qt + 1;
            int h = (total + 1) >> 1;
            if (segid == 0) { seg0 = 0; segn = h; }
            else            { seg0 = h; segn = total - h; }
        } else {
            int j2 = job - 256;
            qt = 15 - (j2 >> 3);
            b  = j2 & 7;
            segid = 0; split = 0; seg0 = 0; segn = qt + 1;
        }
        const int q0 = qt * 64;

        auto issue_kv = [&](int t, int s) {
            uint32_t mb = s ? mbs1 : mbs0;
            uint32_t st = sbase + 2 * (8192 + s * 16384);
            const __nv_bfloat16* kt = g_kT + ((size_t)(b * 32 + t) * 2) * 4096;
            const __nv_bfloat16* vt = g_vT + ((size_t)(b * 32 + t) * 2) * 4096;
            MBAR_EXPECT_TX(mb, 32768);
            BULK(st,             kt,        8192, mb);
            BULK(st + 2 * 4096,  kt + 4096, 8192, mb);
            BULK(st + 2 * 8192,  vt,        8192, mb);
            BULK(st + 2 * 12288, vt + 4096, 8192, mb);
        };

        if (tid == 0) {
            MBAR_INIT(mbq, 1);
            MBAR_INIT(mbs0, 1);
            MBAR_INIT(mbs1, 1);
        }
        __syncthreads();
        if (tid == 0) {
            const __nv_bfloat16* qtl = g_qT + ((size_t)(b * 32 + qt) * 2) * 4096;
            MBAR_EXPECT_TX(mbq, 16384);
            BULK(sbase,            qtl,        8192, mbq);
            BULK(sbase + 2 * 4096, qtl + 4096, 8192, mbq);
            issue_kv(seg0, 0);
            if (segn >= 2) issue_kv(seg0 + 1, 1);
        }

        MBAR_WAIT(mbq, 0);
        uint32_t qfh[4][4], qfl[4][4];
        #pragma unroll
        for (int i = 0; i < 4; i++) {
            int u = qrow * 64 + (((2 * i + kA8) ^ qrx) << 3);
            ldsm4(qfh[i], sbase + 2 * u);
            ldsm4(qfl[i], sbase + 2 * (4096 + u));
        }

        // S-GEMM sub-block for one k-step i against a stage's K arrays
        auto s_block = [&](float sc2[8][4], int i, uint32_t kh_b, uint32_t kl_b) {
            #pragma unroll
            for (int p = 0; p < 4; p++) {
                int row = p * 16 + n_off;
                int u = row * 64 + (((2 * i + kB8) ^ (row & 7)) << 3);
                uint32_t bh[4], bl[4];
                ldsm4(bh, kh_b + 2 * u);
                ldsm4(bl, kl_b + 2 * u);
                #pragma unroll
                for (int hf = 0; hf < 2; hf++) {
                    int nt = p * 2 + hf;
                    mma16816(sc2[nt], qfh[i], bh + hf * 2);
                    mma16816(sc2[nt], qfh[i], bl + hf * 2);
                    mma16816(sc2[nt], qfl[i], bh + hf * 2);
                }
            }
        };

        int ph0 = 0, ph1 = 0;
        float m_i[2] = {-INFINITY, -INFINITY};
        float l_i[2] = {0.f, 0.f};
        float o[8][4];
        #pragma unroll
        for (int nt = 0; nt < 8; nt++)
            #pragma unroll
            for (int i = 0; i < 4; i++) o[nt][i] = 0.f;

        // ---- prologue: wait stage 0, compute S(seg0) ----
        MBAR_WAIT(mbs0, 0); ph0 = 1;
        float sc[8][4];
        #pragma unroll
        for (int nt = 0; nt < 8; nt++)
            #pragma unroll
            for (int i = 0; i < 4; i++) sc[nt][i] = 0.f;
        {
            const uint32_t kh_b = sbase + 2 * 8192;
            const uint32_t kl_b = kh_b + 2 * 4096;
            #pragma unroll
            for (int i = 0; i < 4; i++) s_block(sc, i, kh_b, kl_b);
        }

        for (int tt = 0; tt < segn; tt++) {
            const int t = seg0 + tt;
            const int s = tt & 1;
            const uint32_t vh_b = sbase + 2 * (8192 + s * 16384 + 8192);
            const uint32_t vl_b = vh_b + 2 * 4096;

            if (t == qt) {   // diagonal chunk: causal mask
                int r0 = rw + g;
                #pragma unroll
                for (int nt = 0; nt < 8; nt++) {
                    int c0 = nt * 8 + 2 * tg;
                    if (c0     > r0)     sc[nt][0] = -INFINITY;
                    if (c0 + 1 > r0)     sc[nt][1] = -INFINITY;
                    if (c0     > r0 + 8) sc[nt][2] = -INFINITY;
                    if (c0 + 1 > r0 + 8) sc[nt][3] = -INFINITY;
                }
            }

            float mx0 = -INFINITY, mx1 = -INFINITY;
            #pragma unroll
            for (int nt = 0; nt < 8; nt++) {
                mx0 = fmaxf(mx0, fmaxf(sc[nt][0], sc[nt][1]));
                mx1 = fmaxf(mx1, fmaxf(sc[nt][2], sc[nt][3]));
            }
            mx0 = fmaxf(mx0, __shfl_xor_sync(0xffffffffu, mx0, 1));
            mx0 = fmaxf(mx0, __shfl_xor_sync(0xffffffffu, mx0, 2));
            mx1 = fmaxf(mx1, __shfl_xor_sync(0xffffffffu, mx1, 1));
            mx1 = fmaxf(mx1, __shfl_xor_sync(0xffffffffu, mx1, 2));

            float mn0 = fmaxf(m_i[0], mx0);
            float mn1 = fmaxf(m_i[1], mx1);
            float al0 = ex2(m_i[0] - mn0);
            float al1 = ex2(m_i[1] - mn1);
            m_i[0] = mn0;
            m_i[1] = mn1;
            #pragma unroll
            for (int nt = 0; nt < 8; nt++) {
                o[nt][0] *= al0; o[nt][1] *= al0;
                o[nt][2] *= al1; o[nt][3] *= al1;
            }

            const bool hasNext = (tt + 1 < segn);
            if (hasNext) {   // wait K/V(t+1) — needed by the interleaved S block
                if ((tt + 1) & 1) { MBAR_WAIT(mbs1, ph1); ph1 ^= 1; }
                else              { MBAR_WAIT(mbs0, ph0); ph0 ^= 1; }
            }
            const uint32_t knh_b = sbase + 2 * (8192 + ((tt + 1) & 1) * 16384);
            const uint32_t knl_b = knh_b + 2 * 4096;

            float scn[8][4];
            if (hasNext) {
                #pragma unroll
                for (int nt = 0; nt < 8; nt++)
                    #pragma unroll
                    for (int i = 0; i < 4; i++) scn[nt][i] = 0.f;
            }

            // ---- interleaved: S(t+1) block idx  +  exp/pack/PV(t) block idx ----
            float rs0 = 0.f, rs1 = 0.f;
            #pragma unroll
            for (int idx = 0; idx < 4; idx++) {
                if (hasNext) s_block(scn, idx, knh_b, knl_b);

                int j0 = 2 * idx;
                float p00 = ex2(sc[j0][0] - mn0),     p01 = ex2(sc[j0][1] - mn0);
                float p02 = ex2(sc[j0][2] - mn1),     p03 = ex2(sc[j0][3] - mn1);
                float p10 = ex2(sc[j0 + 1][0] - mn0), p11 = ex2(sc[j0 + 1][1] - mn0);
                float p12 = ex2(sc[j0 + 1][2] - mn1), p13 = ex2(sc[j0 + 1][3] - mn1);
                rs0 += (p00 + p01) + (p10 + p11);
                rs1 += (p02 + p03) + (p12 + p13);
                uint32_t ph[4], pl[4];
                ph[0] = hi2(p00, p01);  pl[0] = lo2(p00, p01);
                ph[1] = hi2(p02, p03);  pl[1] = lo2(p02, p03);
                ph[2] = hi2(p10, p11);  pl[2] = lo2(p10, p11);
                ph[3] = hi2(p12, p13);  pl[3] = lo2(p12, p13);
                #pragma unroll
                for (int p = 0; p < 4; p++) {
                    int row = p * 16 + n_off;
                    int u = row * 64 + (((2 * idx + kB8) ^ (row & 7)) << 3);
                    uint32_t bvh[4], bvl[4];
                    ldsm4(bvh, vh_b + 2 * u);
                    ldsm4(bvl, vl_b + 2 * u);
                    #pragma unroll
                    for (int hf = 0; hf < 2; hf++) {
                        int nt = p * 2 + hf;
                        mma16816(o[nt], ph, bvh + hf * 2);
                        mma16816(o[nt], ph, bvl + hf * 2);
                        mma16816(o[nt], pl, bvh + hf * 2);
                    }
                }
            }
            rs0 += __shfl_xor_sync(0xffffffffu, rs0, 1);
            rs0 += __shfl_xor_sync(0xffffffffu, rs0, 2);
            rs1 += __shfl_xor_sync(0xffffffffu, rs1, 1);
            rs1 += __shfl_xor_sync(0xffffffffu, rs1, 2);
            l_i[0] = l_i[0] * al0 + rs0;
            l_i[1] = l_i[1] * al1 + rs1;

            __syncthreads();   // stage s fully consumed (K last iter, V this iter)
            if (tid == 0 && tt + 2 < segn) issue_kv(seg0 + tt + 2, s);

            if (hasNext) {
                #pragma unroll
                for (int nt = 0; nt < 8; nt++)
                    #pragma unroll
                    for (int i = 0; i < 4; i++) sc[nt][i] = scn[nt][i];
            }
        }

        // ---- epilogue ----
        if (!split) {
            float inv0 = 1.f / l_i[0];
            float inv1 = 1.f / l_i[1];
            int row0 = q0 + rw + g;
            #pragma unroll
            for (int nt = 0; nt < 8; nt++) {
                *(float2*)&out[((size_t)b * TT + row0) * HH + nt * 8 + 2 * tg] =
                    make_float2(o[nt][0] * inv0, o[nt][1] * inv0);
                *(float2*)&out[((size_t)b * TT + row0 + 8) * HH + nt * 8 + 2 * tg] =
                    make_float2(o[nt][2] * inv1, o[nt][3] * inv1);
            }
        } else {
            const int qi   = qt - 16;
            const int tile = b * 16 + qi;
            float* po = g_po + (size_t)(tile * 2 + segid) * 4096;
            float* pm = g_pm + (size_t)(tile * 2 + segid) * 64;
            float* pl = g_pl + (size_t)(tile * 2 + segid) * 64;
            int r0 = rw + g;
            #pragma unroll
            for (int nt = 0; nt < 8; nt++) {
                *(float2*)&po[r0 * 64 + nt * 8 + 2 * tg]       = make_float2(o[nt][0], o[nt][1]);
                *(float2*)&po[(r0 + 8) * 64 + nt * 8 + 2 * tg] = make_float2(o[nt][2], o[nt][3]);
            }
            if (tg == 0) {
                pm[r0] = m_i[0];  pl[r0] = l_i[0];
                pm[r0 + 8] = m_i[1];  pl[r0 + 8] = l_i[1];
            }
            __threadfence();
            __syncthreads();
            if (tid == 0) sLast = atomicAdd(&g_cnt[tile], 1);
            __syncthreads();
            if (sLast == 1) {
                __threadfence();
                const float* po0 = g_po + (size_t)(tile * 2 + 0) * 4096;
                const float* po1 = g_po + (size_t)(tile * 2 + 1) * 4096;
                const float* pm0 = g_pm + (size_t)(tile * 2 + 0) * 64;
                const float* pm1 = g_pm + (size_t)(tile * 2 + 1) * 64;
                const float* pl0 = g_pl + (size_t)(tile * 2 + 0) * 64;
                const float* pl1 = g_pl + (size_t)(tile * 2 + 1) * 64;
                int r  = tid >> 1;
                int c0 = (tid & 1) * 32;
                float m0v = pm0[r], m1v = pm1[r];
                float mm = fmaxf(m0v, m1v);
                float a0 = ex2(m0v - mm), a1 = ex2(m1v - mm);
                float inv = 1.f / (pl0[r] * a0 + pl1[r] * a1);
                float* dst = &out[((size_t)b * TT + q0 + r) * HH + c0];
                #pragma unroll 8
                for (int c = 0; c < 32; c++)
                    dst[c] = (po0[r * 64 + c0 + c] * a0 + po1[r * 64 + c0 + c] * a1) * inv;
                if (tid == 0) g_cnt[tile] = 0;
            }
        }
    }

    if (tid == 0) {
        if (atomicAdd(&g_done, 1) == ATTN_CTAS - 1) {
            g_ctr  = 0;
            g_done = 0;
        }
    }
}

extern "C" void kernel_launch(void* const* d_in, const int* in_sizes, int n_in,
                              void* d_out, int out_size)
{
    const float* x  = (const float*)d_in[0];
    const float* Wq = (const float*)d_in[1];
    const float* Wk = (const float*)d_in[2];
    const float* Wv = (const float*)d_in[3];
    float* out = (float*)d_out;

    cudaFuncSetAttribute(proj_mma_kernel,
                         cudaFuncAttributeMaxDynamicSharedMemorySize, PROJ_SMEM);
    cudaFuncSetAttribute(attn_mma_kernel,
                         cudaFuncAttributeMaxDynamicSharedMemorySize, ATTN_SMEM);

    wprep_kernel<<<96, 256>>>(Wq, Wk, Wv);
    xprep_kernel<<<2048, 256>>>(x);
    proj_mma_kernel<<<BB * TT / 128, 256, PROJ_SMEM>>>();
    attn_mma_kernel<<<ATTN_CTAS, 128, ATTN_SMEM>>>(out);
}